// round 1
// baseline (speedup 1.0000x reference)
#include <cuda_runtime.h>

#define T_LEN 128
#define BATCH 512
#define DIN   768

typedef unsigned long long ull;

// ---------------- scratch (static device arrays; no allocation) ----------------
static __device__ float g_xproj[T_LEN * BATCH * 64];   // bi-LSTM gate pre-activations (x part + bias)
static __device__ float g_h[T_LEN * BATCH * 16];       // concat(h_f, h_b)
static __device__ float g_zproj[T_LEN * BATCH * 64];   // ptr-LSTM gate pre-activations (x part + bias)
static __device__ float g_z[T_LEN * BATCH * 16];       // ptr-LSTM hidden states
static __device__ float g_Wc[DIN * 64];                // combined [k][c] weight for input GEMM
static __device__ float g_bc[64];                      // combined bias

// ---------------- f32x2 helpers (FFMA2) ----------------
__device__ __forceinline__ ull fma2(ull a, ull b, ull c) {
    ull d; asm("fma.rn.f32x2 %0, %1, %2, %3;" : "=l"(d) : "l"(a), "l"(b), "l"(c)); return d;
}
__device__ __forceinline__ ull pack2(float x, float y) {
    ull d; asm("mov.b64 %0, {%1, %2};" : "=l"(d) : "f"(x), "f"(y)); return d;
}
__device__ __forceinline__ float2 unpack2(ull v) {
    float2 r; asm("mov.b64 {%0, %1}, %2;" : "=f"(r.x), "=f"(r.y) : "l"(v)); return r;
}

__device__ __forceinline__ float sigf(float x) {
    return __fdividef(1.f, 1.f + __expf(-x));
}
__device__ __forceinline__ float tanhf_fast(float x) {
    float e = __expf(2.f * x);
    return 1.f - __fdividef(2.f, e + 1.f);
}

// 16-dim dot: sm (16 floats, smem, 16B aligned) . v (8 packed f32x2 in regs)
__device__ __forceinline__ float dot16x2(const float* sm, const ull* v) {
    union U { float4 f; ull u[2]; };
    U q0, q1, q2, q3;
    q0.f = ((const float4*)sm)[0];
    q1.f = ((const float4*)sm)[1];
    q2.f = ((const float4*)sm)[2];
    q3.f = ((const float4*)sm)[3];
    ull a = fma2(q0.u[0], v[0], 0ULL);
    a = fma2(q0.u[1], v[1], a);
    a = fma2(q1.u[0], v[2], a);
    a = fma2(q1.u[1], v[3], a);
    a = fma2(q2.u[0], v[4], a);
    a = fma2(q2.u[1], v[5], a);
    a = fma2(q3.u[0], v[6], a);
    a = fma2(q3.u[1], v[7], a);
    float2 r = unpack2(a);
    return r.x + r.y;
}

// ---------------- K0: build combined input-projection weight ----------------
__global__ __launch_bounds__(256) void k_prep(
    const float* __restrict__ Wih_f, const float* __restrict__ Wih_b,
    const float* __restrict__ bih_f, const float* __restrict__ bhh_f,
    const float* __restrict__ bih_b, const float* __restrict__ bhh_b)
{
    int idx = blockIdx.x * 256 + threadIdx.x;
    if (idx < DIN * 64) {
        int k = idx >> 6, c = idx & 63;
        g_Wc[idx] = (c < 32) ? Wih_f[c * DIN + k] : Wih_b[(c - 32) * DIN + k];
    }
    if (idx < 64) {
        g_bc[idx] = (idx < 32) ? (bih_f[idx] + bhh_f[idx]) : (bih_b[idx - 32] + bhh_b[idx - 32]);
    }
}

// ---------------- K1: xproj = X (65536x768) @ Wc (768x64) + bc ----------------
__global__ __launch_bounds__(256, 2) void k_gemm_xproj(const float* __restrict__ X)
{
    __shared__ float Xs[128][33];
    __shared__ float Ws[32][64];
    const int tid = threadIdx.x;
    const int rowBase = blockIdx.x * 128;
    const int rg = tid >> 3;   // 0..31 (4 rows each)
    const int cg = tid & 7;    // 0..7  (8 cols each)

    ull acc[4][4];
#pragma unroll
    for (int r = 0; r < 4; r++)
#pragma unroll
        for (int c = 0; c < 4; c++) acc[r][c] = 0ULL;

    for (int k0 = 0; k0 < DIN; k0 += 32) {
#pragma unroll
        for (int i = 0; i < 4; i++) {
            int idx = i * 256 + tid;
            int r = idx >> 3, k4 = (idx & 7) * 4;
            float4 v = *(const float4*)(X + (size_t)(rowBase + r) * DIN + k0 + k4);
            Xs[r][k4 + 0] = v.x; Xs[r][k4 + 1] = v.y; Xs[r][k4 + 2] = v.z; Xs[r][k4 + 3] = v.w;
        }
#pragma unroll
        for (int i = 0; i < 2; i++) {
            int idx = i * 256 + tid;
            int kk = idx >> 4, c4 = (idx & 15) * 4;
            *(float4*)&Ws[kk][c4] = *(const float4*)(g_Wc + (k0 + kk) * 64 + c4);
        }
        __syncthreads();
#pragma unroll
        for (int kk = 0; kk < 32; kk++) {
            const ull* wrow = (const ull*)&Ws[kk][cg * 8];
            ull w0 = wrow[0], w1 = wrow[1], w2 = wrow[2], w3 = wrow[3];
#pragma unroll
            for (int r = 0; r < 4; r++) {
                float xv = Xs[rg * 4 + r][kk];
                ull xp = pack2(xv, xv);
                acc[r][0] = fma2(xp, w0, acc[r][0]);
                acc[r][1] = fma2(xp, w1, acc[r][1]);
                acc[r][2] = fma2(xp, w2, acc[r][2]);
                acc[r][3] = fma2(xp, w3, acc[r][3]);
            }
        }
        __syncthreads();
    }
#pragma unroll
    for (int r = 0; r < 4; r++) {
        int row = rowBase + rg * 4 + r;
        float* o = g_xproj + (size_t)row * 64 + cg * 8;
#pragma unroll
        for (int cp = 0; cp < 4; cp++) {
            float2 v = unpack2(acc[r][cp]);
            o[2 * cp + 0] = v.x + g_bc[cg * 8 + 2 * cp + 0];
            o[2 * cp + 1] = v.y + g_bc[cg * 8 + 2 * cp + 1];
        }
    }
}

// ---------------- K2: bi-LSTM scan (8 threads per batch item per direction) ----------------
__global__ __launch_bounds__(256) void k_bilstm(
    const float* __restrict__ Whh_f, const float* __restrict__ Whh_b)
{
    int gt = blockIdx.x * 256 + threadIdx.x;  // 0..8191
    int j   = gt & 7;
    int grp = gt >> 3;        // 0..1023
    int dir = grp >> 9;       // 0 fwd, 1 bwd
    int b   = grp & 511;
    const float* Whh = dir ? Whh_b : Whh_f;

    float w[4][8];
#pragma unroll
    for (int gi = 0; gi < 4; gi++)
#pragma unroll
        for (int k = 0; k < 8; k++) w[gi][k] = Whh[(gi * 8 + j) * 8 + k];

    float h = 0.f, c = 0.f;
    const int lanebase = (threadIdx.x & 31) & ~7;

    for (int s = 0; s < T_LEN; s++) {
        int t = dir ? (T_LEN - 1 - s) : s;
        const float* xp = g_xproj + ((size_t)t * BATCH + b) * 64 + dir * 32;
        float p0 = xp[j], p1 = xp[8 + j], p2 = xp[16 + j], p3 = xp[24 + j];
#pragma unroll
        for (int k = 0; k < 8; k++) {
            float hk = __shfl_sync(0xffffffffu, h, lanebase + k);
            p0 += w[0][k] * hk;
            p1 += w[1][k] * hk;
            p2 += w[2][k] * hk;
            p3 += w[3][k] * hk;
        }
        float ig = sigf(p0), fg = sigf(p1), gg = tanhf_fast(p2), og = sigf(p3);
        c = fg * c + ig * gg;
        h = og * tanhf_fast(c);
        g_h[((size_t)t * BATCH + b) * 16 + dir * 8 + j] = h;
    }
}

// ---------------- K3a: zproj = h (65536x16) @ Wih_p^T (16x64) + bias ----------------
__global__ __launch_bounds__(256) void k_hproj(
    const float* __restrict__ Wih_p, const float* __restrict__ bih_p, const float* __restrict__ bhh_p)
{
    __shared__ float Wp[1024];
    __shared__ float bp[64];
    int tid = threadIdx.x;
    for (int i = tid; i < 1024; i += 256) Wp[i] = Wih_p[i];
    if (tid < 64) bp[tid] = bih_p[tid] + bhh_p[tid];
    __syncthreads();

    int row = blockIdx.x * 256 + tid;
    float hreg[16];
    const float4* hp = (const float4*)(g_h + (size_t)row * 16);
#pragma unroll
    for (int q = 0; q < 4; q++) {
        float4 v = hp[q];
        hreg[4 * q + 0] = v.x; hreg[4 * q + 1] = v.y; hreg[4 * q + 2] = v.z; hreg[4 * q + 3] = v.w;
    }
    float* o = g_zproj + (size_t)row * 64;
#pragma unroll
    for (int r = 0; r < 64; r += 4) {
        float a0 = bp[r], a1 = bp[r + 1], a2 = bp[r + 2], a3 = bp[r + 3];
#pragma unroll
        for (int k = 0; k < 16; k++) {
            float hk = hreg[k];
            a0 += Wp[(r + 0) * 16 + k] * hk;
            a1 += Wp[(r + 1) * 16 + k] * hk;
            a2 += Wp[(r + 2) * 16 + k] * hk;
            a3 += Wp[(r + 3) * 16 + k] * hk;
        }
        ((float4*)o)[r >> 2] = make_float4(a0, a1, a2, a3);
    }
}

// ---------------- K3b: ptr-LSTM scan (16 threads per batch item) ----------------
__global__ __launch_bounds__(256) void k_ptrlstm(const float* __restrict__ Whh_p)
{
    int gt = blockIdx.x * 256 + threadIdx.x;  // 0..8191
    int j = gt & 15;
    int b = gt >> 4;  // 0..511

    float w[4][16];
#pragma unroll
    for (int gi = 0; gi < 4; gi++)
#pragma unroll
        for (int k = 0; k < 16; k++) w[gi][k] = Whh_p[(gi * 16 + j) * 16 + k];

    float h = 0.f, c = 0.f;
    const int lanebase = (threadIdx.x & 31) & ~15;

    for (int t = 0; t < T_LEN; t++) {
        const float* zp = g_zproj + ((size_t)t * BATCH + b) * 64;
        float p0 = zp[j], p1 = zp[16 + j], p2 = zp[32 + j], p3 = zp[48 + j];
#pragma unroll
        for (int k = 0; k < 16; k++) {
            float hk = __shfl_sync(0xffffffffu, h, lanebase + k);
            p0 += w[0][k] * hk;
            p1 += w[1][k] * hk;
            p2 += w[2][k] * hk;
            p3 += w[3][k] * hk;
        }
        float ig = sigf(p0), fg = sigf(p1), gg = tanhf_fast(p2), og = sigf(p3);
        c = fg * c + ig * gg;
        h = og * tanhf_fast(c);
        g_z[((size_t)t * BATCH + b) * 16 + j] = h;
    }
}

// ---------------- K4: attention + output head, one CTA per t ----------------
// attn[b,c] = h_b . z_c ; w = softmax over b (column-wise); ctx[b] = sum_c w[b,c] h[c]
// |logit| <= 16 (LSTM outputs bounded by 1) -> exp without max subtraction is safe.
__global__ __launch_bounds__(512, 1) void k_attn(
    const float* __restrict__ W_h, const float* __restrict__ W_e,
    const float* __restrict__ W_v, float* __restrict__ out)
{
    extern __shared__ float dsm[];
    float* sh = dsm;          // 512*16 floats (h_t, later overwritten by h/s_c)
    float* sz = dsm + 8192;   // 512*16 floats (z_t)
    __shared__ float sWh[256], sWe[256], sWv[16];

    const int t = blockIdx.x, tid = threadIdx.x;
    const float* hg = g_h + (size_t)t * 8192;
    const float* zg = g_z + (size_t)t * 8192;
    for (int i = tid; i < 2048; i += 512) {
        ((float4*)sh)[i] = ((const float4*)hg)[i];
        ((float4*)sz)[i] = ((const float4*)zg)[i];
    }
    if (tid < 256) { sWh[tid] = W_h[tid]; sWe[tid] = W_e[tid]; }
    if (tid < 16)  sWv[tid] = W_v[tid];
    __syncthreads();

    // pass 1: thread owns column c = tid, computes s_c = sum_b exp(h_b . z_c)
    ull zc2[8];
    {
        const float* zr = sz + tid * 16;
#pragma unroll
        for (int q = 0; q < 4; q++) {
            union { float4 f; ull u[2]; } w; w.f = ((const float4*)zr)[q];
            zc2[2 * q] = w.u[0]; zc2[2 * q + 1] = w.u[1];
        }
    }
    float ssum = 0.f;
#pragma unroll 4
    for (int bb = 0; bb < 512; bb++)
        ssum += __expf(dot16x2(sh + bb * 16, zc2));
    float inv = __fdividef(1.f, ssum);

    // stash original h row in regs before in-place scaling
    ull hb2[8]; float hb[16];
    {
        const float* hr = sh + tid * 16;
#pragma unroll
        for (int q = 0; q < 4; q++) {
            union { float4 f; ull u[2]; } w; w.f = ((const float4*)hr)[q];
            hb2[2 * q] = w.u[0]; hb2[2 * q + 1] = w.u[1];
            hb[4 * q + 0] = w.f.x; hb[4 * q + 1] = w.f.y; hb[4 * q + 2] = w.f.z; hb[4 * q + 3] = w.f.w;
        }
    }
    __syncthreads();
    {
        float* hr = sh + tid * 16;
#pragma unroll
        for (int q = 0; q < 4; q++)
            ((float4*)hr)[q] = make_float4(hb[4 * q] * inv, hb[4 * q + 1] * inv,
                                           hb[4 * q + 2] * inv, hb[4 * q + 3] * inv);
    }
    __syncthreads();

    // pass 2: thread owns row b = tid: ctx[b] = sum_c exp(h_b . z_c) * (h_c / s_c)
    ull ctx2[8];
#pragma unroll
    for (int q = 0; q < 8; q++) ctx2[q] = 0ULL;
#pragma unroll 2
    for (int cc = 0; cc < 512; cc++) {
        float s = dot16x2(sz + cc * 16, hb2);
        float e = __expf(s);
        ull e2 = pack2(e, e);
        const float* hd = sh + cc * 16;
#pragma unroll
        for (int q = 0; q < 4; q++) {
            union { float4 f; ull u[2]; } w; w.f = ((const float4*)hd)[q];
            ctx2[2 * q]     = fma2(e2, w.u[0], ctx2[2 * q]);
            ctx2[2 * q + 1] = fma2(e2, w.u[1], ctx2[2 * q + 1]);
        }
    }
    float ctx[16];
#pragma unroll
    for (int q = 0; q < 8; q++) {
        float2 v = unpack2(ctx2[q]);
        ctx[2 * q] = v.x; ctx[2 * q + 1] = v.y;
    }

    // head: u = tanh(h W_h^T + ctx W_e^T); p = sigmoid(u . W_v)
    float pv = 0.f;
#pragma unroll
    for (int r = 0; r < 16; r++) {
        float a = 0.f;
#pragma unroll
        for (int k = 0; k < 16; k++)
            a += sWh[r * 16 + k] * hb[k] + sWe[r * 16 + k] * ctx[k];
        pv += sWv[r] * tanhf_fast(a);
    }
    out[(size_t)t * BATCH + tid] = sigf(pv);
}

// ---------------- launch ----------------
extern "C" void kernel_launch(void* const* d_in, const int* in_sizes, int n_in,
                              void* d_out, int out_size)
{
    const float* X     = (const float*)d_in[0];
    const float* Wih_f = (const float*)d_in[1];
    const float* Whh_f = (const float*)d_in[2];
    const float* bih_f = (const float*)d_in[3];
    const float* bhh_f = (const float*)d_in[4];
    const float* Wih_b = (const float*)d_in[5];
    const float* Whh_b = (const float*)d_in[6];
    const float* bih_b = (const float*)d_in[7];
    const float* bhh_b = (const float*)d_in[8];
    const float* Wih_p = (const float*)d_in[9];
    const float* Whh_p = (const float*)d_in[10];
    const float* bih_p = (const float*)d_in[11];
    const float* bhh_p = (const float*)d_in[12];
    const float* W_h   = (const float*)d_in[13];
    const float* W_e   = (const float*)d_in[14];
    const float* W_v   = (const float*)d_in[15];
    float* out = (float*)d_out;

    cudaFuncSetAttribute((const void*)k_attn, cudaFuncAttributeMaxDynamicSharedMemorySize, 72 * 1024);

    k_prep<<<(DIN * 64 + 255) / 256, 256>>>(Wih_f, Wih_b, bih_f, bhh_f, bih_b, bhh_b);
    k_gemm_xproj<<<(T_LEN * BATCH) / 128, 256>>>(X);
    k_bilstm<<<32, 256>>>(Whh_f, Whh_b);
    k_hproj<<<(T_LEN * BATCH) / 256, 256>>>(Wih_p, bih_p, bhh_p);
    k_ptrlstm<<<32, 256>>>(Whh_p);
    k_attn<<<T_LEN, 512, 65536>>>(W_h, W_e, W_v, out);
}

// round 2
// speedup vs baseline: 1.4434x; 1.4434x over previous
#include <cuda_runtime.h>

#define T_LEN 128
#define BATCH 512
#define DIN   768

typedef unsigned long long ull;
typedef unsigned int uint32;

// ---------------- scratch (static device arrays; no allocation) ----------------
static __device__ float g_xproj[T_LEN * BATCH * 64];   // bi-LSTM gate pre-activations (x part + bias)
static __device__ float g_h[T_LEN * BATCH * 16];       // concat(h_f, h_b)
static __device__ float g_z[T_LEN * BATCH * 16];       // ptr-LSTM hidden states
static __device__ float g_Wh[DIN * 64];                // tf32-hi of combined [k][c] weight
static __device__ float g_Wl[DIN * 64];                // tf32-lo residual
static __device__ float g_bc[64];                      // combined bias

// ---------------- f32x2 helpers (FFMA2) ----------------
__device__ __forceinline__ ull fma2(ull a, ull b, ull c) {
    ull d; asm("fma.rn.f32x2 %0, %1, %2, %3;" : "=l"(d) : "l"(a), "l"(b), "l"(c)); return d;
}
__device__ __forceinline__ ull pack2(float x, float y) {
    ull d; asm("mov.b64 %0, {%1, %2};" : "=l"(d) : "f"(x), "f"(y)); return d;
}
__device__ __forceinline__ float2 unpack2(ull v) {
    float2 r; asm("mov.b64 {%0, %1}, %2;" : "=f"(r.x), "=f"(r.y) : "l"(v)); return r;
}
__device__ __forceinline__ uint32 tf32_of(float x) {
    uint32 r; asm("cvt.rna.tf32.f32 %0, %1;" : "=r"(r) : "f"(x)); return r;
}

__device__ __forceinline__ float sigf(float x) {
    return __fdividef(1.f, 1.f + __expf(-x));
}
__device__ __forceinline__ float tanhf_fast(float x) {
    float e = __expf(2.f * x);
    return 1.f - __fdividef(2.f, e + 1.f);
}

// tf32 mma m16n8k8, row.col, f32 accumulate
__device__ __forceinline__ void mma_tf32(float* d, const uint32* a, const uint32* b) {
    asm volatile(
        "mma.sync.aligned.m16n8k8.row.col.f32.tf32.tf32.f32 "
        "{%0,%1,%2,%3}, {%4,%5,%6,%7}, {%8,%9}, {%0,%1,%2,%3};"
        : "+f"(d[0]), "+f"(d[1]), "+f"(d[2]), "+f"(d[3])
        : "r"(a[0]), "r"(a[1]), "r"(a[2]), "r"(a[3]), "r"(b[0]), "r"(b[1]));
}

// 16-dim dot: sm (16 floats, smem, 16B aligned) . v (8 packed f32x2 in regs)
__device__ __forceinline__ float dot16x2(const float* sm, const ull* v) {
    union U { float4 f; ull u[2]; };
    U q0, q1, q2, q3;
    q0.f = ((const float4*)sm)[0];
    q1.f = ((const float4*)sm)[1];
    q2.f = ((const float4*)sm)[2];
    q3.f = ((const float4*)sm)[3];
    ull a = fma2(q0.u[0], v[0], 0ULL);
    a = fma2(q0.u[1], v[1], a);
    a = fma2(q1.u[0], v[2], a);
    a = fma2(q1.u[1], v[3], a);
    a = fma2(q2.u[0], v[4], a);
    a = fma2(q2.u[1], v[5], a);
    a = fma2(q3.u[0], v[6], a);
    a = fma2(q3.u[1], v[7], a);
    float2 r = unpack2(a);
    return r.x + r.y;
}

// ---------------- K0: build combined input-projection weight (tf32 hi/lo) ----------------
__global__ __launch_bounds__(256) void k_prep(
    const float* __restrict__ Wih_f, const float* __restrict__ Wih_b,
    const float* __restrict__ bih_f, const float* __restrict__ bhh_f,
    const float* __restrict__ bih_b, const float* __restrict__ bhh_b)
{
    int idx = blockIdx.x * 256 + threadIdx.x;
    if (idx < DIN * 64) {
        int k = idx >> 6, c = idx & 63;
        float w = (c < 32) ? Wih_f[c * DIN + k] : Wih_b[(c - 32) * DIN + k];
        float hi = __uint_as_float(tf32_of(w));
        g_Wh[idx] = hi;
        g_Wl[idx] = __uint_as_float(tf32_of(w - hi));
    }
    if (idx < 64) {
        g_bc[idx] = (idx < 32) ? (bih_f[idx] + bhh_f[idx]) : (bih_b[idx - 32] + bhh_b[idx - 32]);
    }
}

// ---------------- K1: xproj = X (65536x768) @ Wc (768x64) + bc  (tf32 tensor cores) ----------------
// smem layout (floats): Xh[128][36] @0, Xl[128][36] @4608, Wh[32][72] @9216, Wl[32][72] @11520
#define GEMM_SMEM_FLOATS 13824
__global__ __launch_bounds__(256, 2) void k_gemm_xproj(const float* __restrict__ X)
{
    extern __shared__ float sm[];
    float* Xh = sm;
    float* Xl = sm + 4608;
    float* Whs = sm + 9216;
    float* Wls = sm + 11520;

    const int tid = threadIdx.x;
    const int rowBase = blockIdx.x * 128;
    const int w = tid >> 5;        // warp 0..7 -> rows w*16..w*16+15
    const int lane = tid & 31;
    const int g = lane >> 2;       // groupID 0..7
    const int t4 = lane & 3;       // threadID in group

    float acc[8][4];
#pragma unroll
    for (int nt = 0; nt < 8; nt++)
#pragma unroll
        for (int q = 0; q < 4; q++) acc[nt][q] = 0.f;

    for (int k0 = 0; k0 < DIN; k0 += 32) {
        // stage X (128x32) with tf32 hi/lo split
#pragma unroll
        for (int i = 0; i < 4; i++) {
            int idx = i * 256 + tid;            // 0..1023 float4s
            int r = idx >> 3, c4 = (idx & 7) * 4;
            float4 v = *(const float4*)(X + (size_t)(rowBase + r) * DIN + k0 + c4);
            float hx = __uint_as_float(tf32_of(v.x));
            float hy = __uint_as_float(tf32_of(v.y));
            float hz = __uint_as_float(tf32_of(v.z));
            float hw = __uint_as_float(tf32_of(v.w));
            *(float4*)(Xh + r * 36 + c4) = make_float4(hx, hy, hz, hw);
            *(float4*)(Xl + r * 36 + c4) = make_float4(
                __uint_as_float(tf32_of(v.x - hx)), __uint_as_float(tf32_of(v.y - hy)),
                __uint_as_float(tf32_of(v.z - hz)), __uint_as_float(tf32_of(v.w - hw)));
        }
        // stage W (32x64) hi/lo
#pragma unroll
        for (int i = 0; i < 2; i++) {
            int idx = i * 256 + tid;            // 0..511 float4s
            int kk = idx >> 4, c4 = (idx & 15) * 4;
            *(float4*)(Whs + kk * 72 + c4) = *(const float4*)(g_Wh + (k0 + kk) * 64 + c4);
            *(float4*)(Wls + kk * 72 + c4) = *(const float4*)(g_Wl + (k0 + kk) * 64 + c4);
        }
        __syncthreads();

#pragma unroll
        for (int ks = 0; ks < 4; ks++) {
            const int col = ks * 8 + t4;
            const int r0 = (w * 16 + g) * 36;
            uint32 ah[4], al[4];
            ah[0] = __float_as_uint(Xh[r0 + col]);
            ah[1] = __float_as_uint(Xh[r0 + 8 * 36 + col]);
            ah[2] = __float_as_uint(Xh[r0 + col + 4]);
            ah[3] = __float_as_uint(Xh[r0 + 8 * 36 + col + 4]);
            al[0] = __float_as_uint(Xl[r0 + col]);
            al[1] = __float_as_uint(Xl[r0 + 8 * 36 + col]);
            al[2] = __float_as_uint(Xl[r0 + col + 4]);
            al[3] = __float_as_uint(Xl[r0 + 8 * 36 + col + 4]);
            const int kb0 = (ks * 8 + t4) * 72;
            const int kb1 = (ks * 8 + t4 + 4) * 72;
#pragma unroll
            for (int nt = 0; nt < 8; nt++) {
                int n = nt * 8 + g;
                uint32 bh[2], bl[2];
                bh[0] = __float_as_uint(Whs[kb0 + n]);
                bh[1] = __float_as_uint(Whs[kb1 + n]);
                bl[0] = __float_as_uint(Wls[kb0 + n]);
                bl[1] = __float_as_uint(Wls[kb1 + n]);
                mma_tf32(acc[nt], ah, bh);
                mma_tf32(acc[nt], ah, bl);
                mma_tf32(acc[nt], al, bh);
            }
        }
        __syncthreads();
    }

    // write out with bias
    const int r0 = rowBase + w * 16 + g;
#pragma unroll
    for (int nt = 0; nt < 8; nt++) {
        int cbase = nt * 8 + 2 * t4;
        float b0 = g_bc[cbase], b1 = g_bc[cbase + 1];
        *(float2*)(g_xproj + (size_t)r0 * 64 + cbase) = make_float2(acc[nt][0] + b0, acc[nt][1] + b1);
        *(float2*)(g_xproj + (size_t)(r0 + 8) * 64 + cbase) = make_float2(acc[nt][2] + b0, acc[nt][3] + b1);
    }
}

// ---------------- K2: bi-LSTM scan (8 threads per batch item per direction), prefetched ----------------
__global__ __launch_bounds__(256) void k_bilstm(
    const float* __restrict__ Whh_f, const float* __restrict__ Whh_b)
{
    int gt = blockIdx.x * 256 + threadIdx.x;  // 0..8191
    int j   = gt & 7;
    int grp = gt >> 3;        // 0..1023
    int dir = grp >> 9;       // 0 fwd, 1 bwd
    int b   = grp & 511;
    const float* Whh = dir ? Whh_b : Whh_f;

    float w[4][8];
#pragma unroll
    for (int gi = 0; gi < 4; gi++)
#pragma unroll
        for (int k = 0; k < 8; k++) w[gi][k] = Whh[(gi * 8 + j) * 8 + k];

    float h = 0.f, c = 0.f;
    const int lanebase = (threadIdx.x & 31) & ~7;

    // prefetch step 0
    int t0 = dir ? (T_LEN - 1) : 0;
    const float* xp = g_xproj + ((size_t)t0 * BATCH + b) * 64 + dir * 32;
    float n0 = xp[j], n1 = xp[8 + j], n2 = xp[16 + j], n3 = xp[24 + j];

    for (int s = 0; s < T_LEN; s++) {
        int t = dir ? (T_LEN - 1 - s) : s;
        float p0 = n0, p1 = n1, p2 = n2, p3 = n3;
        if (s < T_LEN - 1) {
            int tn = dir ? (T_LEN - 2 - s) : (s + 1);
            const float* xn = g_xproj + ((size_t)tn * BATCH + b) * 64 + dir * 32;
            n0 = xn[j]; n1 = xn[8 + j]; n2 = xn[16 + j]; n3 = xn[24 + j];
        }
#pragma unroll
        for (int k = 0; k < 8; k++) {
            float hk = __shfl_sync(0xffffffffu, h, lanebase + k);
            p0 += w[0][k] * hk;
            p1 += w[1][k] * hk;
            p2 += w[2][k] * hk;
            p3 += w[3][k] * hk;
        }
        float ig = sigf(p0), fg = sigf(p1), gg = tanhf_fast(p2), og = sigf(p3);
        c = fg * c + ig * gg;
        h = og * tanhf_fast(c);
        g_h[((size_t)t * BATCH + b) * 16 + dir * 8 + j] = h;
    }
}

// ---------------- K3: ptr-LSTM scan with fused input projection ----------------
// input x_t = h_t[b] (16-dim). Each thread j owns gate rows {j,16+j,32+j,48+j},
// weights [Wih | Whh] = 4x32 in registers. 32-dim [x;h] gathered via shuffles.
__global__ __launch_bounds__(256, 1) void k_ptrlstm(
    const float* __restrict__ Wih_p, const float* __restrict__ Whh_p,
    const float* __restrict__ bih_p, const float* __restrict__ bhh_p)
{
    int gt = blockIdx.x * 256 + threadIdx.x;  // 0..8191
    int j = gt & 15;
    int b = gt >> 4;  // 0..511

    float w[4][32];
    float bias[4];
#pragma unroll
    for (int gi = 0; gi < 4; gi++) {
        int row = gi * 16 + j;
#pragma unroll
        for (int k = 0; k < 16; k++) w[gi][k] = Wih_p[row * 16 + k];
#pragma unroll
        for (int k = 0; k < 16; k++) w[gi][16 + k] = Whh_p[row * 16 + k];
        bias[gi] = bih_p[row] + bhh_p[row];
    }

    float h = 0.f, c = 0.f;
    const int lanebase = (threadIdx.x & 31) & ~15;

    float xnext = g_h[(size_t)b * 16 + j];  // t = 0

    for (int t = 0; t < T_LEN; t++) {
        float xv = xnext;
        if (t < T_LEN - 1) xnext = g_h[((size_t)(t + 1) * BATCH + b) * 16 + j];
        float p0 = bias[0], p1 = bias[1], p2 = bias[2], p3 = bias[3];
#pragma unroll
        for (int k = 0; k < 16; k++) {
            float xk = __shfl_sync(0xffffffffu, xv, lanebase + k);
            p0 += w[0][k] * xk;
            p1 += w[1][k] * xk;
            p2 += w[2][k] * xk;
            p3 += w[3][k] * xk;
        }
#pragma unroll
        for (int k = 0; k < 16; k++) {
            float hk = __shfl_sync(0xffffffffu, h, lanebase + k);
            p0 += w[0][16 + k] * hk;
            p1 += w[1][16 + k] * hk;
            p2 += w[2][16 + k] * hk;
            p3 += w[3][16 + k] * hk;
        }
        float ig = sigf(p0), fg = sigf(p1), gg = tanhf_fast(p2), og = sigf(p3);
        c = fg * c + ig * gg;
        h = og * tanhf_fast(c);
        g_z[((size_t)t * BATCH + b) * 16 + j] = h;
    }
}

// ---------------- K4: attention + output head, one CTA per t ----------------
// attn[b,c] = h_b . z_c ; w = softmax over b (column-wise); ctx[b] = sum_c w[b,c] h[c]
// |logit| <= 16 (LSTM outputs bounded by 1) -> exp without max subtraction is safe.
__global__ __launch_bounds__(512, 1) void k_attn(
    const float* __restrict__ W_h, const float* __restrict__ W_e,
    const float* __restrict__ W_v, float* __restrict__ out)
{
    extern __shared__ float dsm[];
    float* sh = dsm;          // 512*16 floats (h_t, later overwritten by h/s_c)
    float* sz = dsm + 8192;   // 512*16 floats (z_t)
    __shared__ float sWh[256], sWe[256], sWv[16];

    const int t = blockIdx.x, tid = threadIdx.x;
    const float* hg = g_h + (size_t)t * 8192;
    const float* zg = g_z + (size_t)t * 8192;
    for (int i = tid; i < 2048; i += 512) {
        ((float4*)sh)[i] = ((const float4*)hg)[i];
        ((float4*)sz)[i] = ((const float4*)zg)[i];
    }
    if (tid < 256) { sWh[tid] = W_h[tid]; sWe[tid] = W_e[tid]; }
    if (tid < 16)  sWv[tid] = W_v[tid];
    __syncthreads();

    // pass 1: thread owns column c = tid, computes s_c = sum_b exp(h_b . z_c)
    ull zc2[8];
    {
        const float* zr = sz + tid * 16;
#pragma unroll
        for (int q = 0; q < 4; q++) {
            union { float4 f; ull u[2]; } wv; wv.f = ((const float4*)zr)[q];
            zc2[2 * q] = wv.u[0]; zc2[2 * q + 1] = wv.u[1];
        }
    }
    float s0 = 0.f, s1 = 0.f;
#pragma unroll 4
    for (int bb = 0; bb < 512; bb += 2) {
        s0 += __expf(dot16x2(sh + bb * 16, zc2));
        s1 += __expf(dot16x2(sh + bb * 16 + 16, zc2));
    }
    float inv = __fdividef(1.f, s0 + s1);

    // stash original h row in regs before in-place scaling
    ull hb2[8]; float hb[16];
    {
        const float* hr = sh + tid * 16;
#pragma unroll
        for (int q = 0; q < 4; q++) {
            union { float4 f; ull u[2]; } wv; wv.f = ((const float4*)hr)[q];
            hb2[2 * q] = wv.u[0]; hb2[2 * q + 1] = wv.u[1];
            hb[4 * q + 0] = wv.f.x; hb[4 * q + 1] = wv.f.y; hb[4 * q + 2] = wv.f.z; hb[4 * q + 3] = wv.f.w;
        }
    }
    __syncthreads();
    {
        float* hr = sh + tid * 16;
#pragma unroll
        for (int q = 0; q < 4; q++)
            ((float4*)hr)[q] = make_float4(hb[4 * q] * inv, hb[4 * q + 1] * inv,
                                           hb[4 * q + 2] * inv, hb[4 * q + 3] * inv);
    }
    __syncthreads();

    // pass 2: thread owns row b = tid: ctx[b] = sum_c exp(h_b . z_c) * (h_c / s_c)
    ull ctx2[8];
#pragma unroll
    for (int q = 0; q < 8; q++) ctx2[q] = 0ULL;
#pragma unroll 2
    for (int cc = 0; cc < 512; cc++) {
        float s = dot16x2(sz + cc * 16, hb2);
        float e = __expf(s);
        ull e2 = pack2(e, e);
        const float* hd = sh + cc * 16;
#pragma unroll
        for (int q = 0; q < 4; q++) {
            union { float4 f; ull u[2]; } wv; wv.f = ((const float4*)hd)[q];
            ctx2[2 * q]     = fma2(e2, wv.u[0], ctx2[2 * q]);
            ctx2[2 * q + 1] = fma2(e2, wv.u[1], ctx2[2 * q + 1]);
        }
    }
    float ctx[16];
#pragma unroll
    for (int q = 0; q < 8; q++) {
        float2 v = unpack2(ctx2[q]);
        ctx[2 * q] = v.x; ctx[2 * q + 1] = v.y;
    }

    // head: u = tanh(h W_h^T + ctx W_e^T); p = sigmoid(u . W_v)
    float pv = 0.f;
#pragma unroll
    for (int r = 0; r < 16; r++) {
        float a = 0.f;
#pragma unroll
        for (int k = 0; k < 16; k++)
            a += sWh[r * 16 + k] * hb[k] + sWe[r * 16 + k] * ctx[k];
        pv += sWv[r] * tanhf_fast(a);
    }
    out[(size_t)t * BATCH + tid] = sigf(pv);
}

// ---------------- launch ----------------
extern "C" void kernel_launch(void* const* d_in, const int* in_sizes, int n_in,
                              void* d_out, int out_size)
{
    const float* X     = (const float*)d_in[0];
    const float* Wih_f = (const float*)d_in[1];
    const float* Whh_f = (const float*)d_in[2];
    const float* bih_f = (const float*)d_in[3];
    const float* bhh_f = (const float*)d_in[4];
    const float* Wih_b = (const float*)d_in[5];
    const float* Whh_b = (const float*)d_in[6];
    const float* bih_b = (const float*)d_in[7];
    const float* bhh_b = (const float*)d_in[8];
    const float* Wih_p = (const float*)d_in[9];
    const float* Whh_p = (const float*)d_in[10];
    const float* bih_p = (const float*)d_in[11];
    const float* bhh_p = (const float*)d_in[12];
    const float* W_h   = (const float*)d_in[13];
    const float* W_e   = (const float*)d_in[14];
    const float* W_v   = (const float*)d_in[15];
    float* out = (float*)d_out;

    static int attr_set = 0;
    cudaFuncSetAttribute((const void*)k_attn, cudaFuncAttributeMaxDynamicSharedMemorySize, 72 * 1024);
    cudaFuncSetAttribute((const void*)k_gemm_xproj, cudaFuncAttributeMaxDynamicSharedMemorySize, 60 * 1024);
    (void)attr_set;

    k_prep<<<(DIN * 64 + 255) / 256, 256>>>(Wih_f, Wih_b, bih_f, bhh_f, bih_b, bhh_b);
    k_gemm_xproj<<<(T_LEN * BATCH) / 128, 256, GEMM_SMEM_FLOATS * 4>>>(X);
    k_bilstm<<<32, 256>>>(Whh_f, Whh_b);
    k_ptrlstm<<<32, 256>>>(Wih_p, Whh_p, bih_p, bhh_p);
    k_attn<<<T_LEN, 512, 65536>>>(W_h, W_e, W_v, out);
}

// round 3
// speedup vs baseline: 1.9343x; 1.3401x over previous
#include <cuda_runtime.h>
#include <cuda_bf16.h>

#define T_LEN 128
#define BATCH 512
#define DIN   768

typedef unsigned long long ull;
typedef unsigned int uint32;

// ---------------- scratch (static device arrays; no allocation) ----------------
static __device__ float g_xproj[T_LEN * BATCH * 64];   // bi-LSTM gate pre-activations (x part + bias)
static __device__ float g_h[T_LEN * BATCH * 16];       // concat(h_f, h_b)
static __device__ float g_zproj[T_LEN * BATCH * 64];   // ptr-LSTM x-projection + bias
static __device__ float g_z[T_LEN * BATCH * 16];       // ptr-LSTM hidden states
static __device__ __nv_bfloat16 g_Wbh[64 * DIN];       // bf16-hi of combined weight, [n][k]
static __device__ __nv_bfloat16 g_Wbl[64 * DIN];       // bf16-lo residual, [n][k]
static __device__ float g_bc[64];                      // combined bias

// ---------------- f32x2 helpers (FFMA2) ----------------
__device__ __forceinline__ ull fma2(ull a, ull b, ull c) {
    ull d; asm("fma.rn.f32x2 %0, %1, %2, %3;" : "=l"(d) : "l"(a), "l"(b), "l"(c)); return d;
}
__device__ __forceinline__ ull pack2(float x, float y) {
    ull d; asm("mov.b64 %0, {%1, %2};" : "=l"(d) : "f"(x), "f"(y)); return d;
}
__device__ __forceinline__ float2 unpack2(ull v) {
    float2 r; asm("mov.b64 {%0, %1}, %2;" : "=f"(r.x), "=f"(r.y) : "l"(v)); return r;
}
__device__ __forceinline__ float ex2f(float x) {
    float r; asm("ex2.approx.ftz.f32 %0, %1;" : "=f"(r) : "f"(x)); return r;
}

__device__ __forceinline__ float sigf(float x) {
    return __fdividef(1.f, 1.f + __expf(-x));
}
__device__ __forceinline__ float tanhf_fast(float x) {
    float e = __expf(2.f * x);
    return 1.f - __fdividef(2.f, e + 1.f);
}

// bf16 mma m16n8k16, row.col, f32 accumulate
__device__ __forceinline__ void mma_bf16(float* d, const uint32* a, const uint32* b) {
    asm volatile(
        "mma.sync.aligned.m16n8k16.row.col.f32.bf16.bf16.f32 "
        "{%0,%1,%2,%3}, {%4,%5,%6,%7}, {%8,%9}, {%0,%1,%2,%3};"
        : "+f"(d[0]), "+f"(d[1]), "+f"(d[2]), "+f"(d[3])
        : "r"(a[0]), "r"(a[1]), "r"(a[2]), "r"(a[3]), "r"(b[0]), "r"(b[1]));
}

// 16-dim dot: sm (16 floats, smem, 16B aligned) . v (8 packed f32x2 in regs)
__device__ __forceinline__ float dot16x2(const float* sm, const ull* v) {
    union U { float4 f; ull u[2]; };
    U q0, q1, q2, q3;
    q0.f = ((const float4*)sm)[0];
    q1.f = ((const float4*)sm)[1];
    q2.f = ((const float4*)sm)[2];
    q3.f = ((const float4*)sm)[3];
    ull a = fma2(q0.u[0], v[0], 0ULL);
    a = fma2(q0.u[1], v[1], a);
    a = fma2(q1.u[0], v[2], a);
    a = fma2(q1.u[1], v[3], a);
    a = fma2(q2.u[0], v[4], a);
    a = fma2(q2.u[1], v[5], a);
    a = fma2(q3.u[0], v[6], a);
    a = fma2(q3.u[1], v[7], a);
    float2 r = unpack2(a);
    return r.x + r.y;
}

// ---------------- K0: build combined weight, bf16 hi/lo, transposed [n][k] ----------------
__global__ __launch_bounds__(256) void k_prep(
    const float* __restrict__ Wih_f, const float* __restrict__ Wih_b,
    const float* __restrict__ bih_f, const float* __restrict__ bhh_f,
    const float* __restrict__ bih_b, const float* __restrict__ bhh_b)
{
    int n = blockIdx.y;
    int k = blockIdx.x * 256 + threadIdx.x;
    float w = (n < 32) ? Wih_f[n * DIN + k] : Wih_b[(n - 32) * DIN + k];
    __nv_bfloat16 hi = __float2bfloat16_rn(w);
    float res = w - __bfloat162float(hi);
    g_Wbh[n * DIN + k] = hi;
    g_Wbl[n * DIN + k] = __float2bfloat16_rn(res);
    if (blockIdx.x == 0 && blockIdx.y == 0 && threadIdx.x < 64) {
        int i = threadIdx.x;
        g_bc[i] = (i < 32) ? (bih_f[i] + bhh_f[i]) : (bih_b[i - 32] + bhh_b[i - 32]);
    }
}

// ---------------- K1: xproj = X (65536x768) @ Wc (768x64) + bc  (bf16 tensor cores) ----------------
#define XPITCH 40
__global__ __launch_bounds__(256, 2) void k_gemm_xproj(const float* __restrict__ X)
{
    __shared__ __nv_bfloat16 Xh[128 * XPITCH];
    __shared__ __nv_bfloat16 Xl[128 * XPITCH];
    __shared__ __nv_bfloat16 Wh[64 * XPITCH];
    __shared__ __nv_bfloat16 Wl[64 * XPITCH];

    const int tid = threadIdx.x;
    const int rowBase = blockIdx.x * 128;
    const int w = tid >> 5;        // warp 0..7 -> rows w*16..w*16+15
    const int lane = tid & 31;
    const int g = lane >> 2;       // groupID 0..7
    const int t4 = lane & 3;       // threadID in group

    float acc[8][4];
#pragma unroll
    for (int nt = 0; nt < 8; nt++)
#pragma unroll
        for (int q = 0; q < 4; q++) acc[nt][q] = 0.f;

    float4 vx[4];
    ull vwh[2], vwl[2];

    // prefetch chunk 0
#pragma unroll
    for (int i = 0; i < 4; i++) {
        int idx = i * 256 + tid;
        int r = idx >> 3, k4 = (idx & 7) * 4;
        vx[i] = *(const float4*)(X + (size_t)(rowBase + r) * DIN + k4);
    }
#pragma unroll
    for (int i = 0; i < 2; i++) {
        int idx = i * 256 + tid;
        int n = idx >> 3, k8 = (idx & 7) * 4;
        vwh[i] = *(const ull*)(g_Wbh + n * DIN + k8);
        vwl[i] = *(const ull*)(g_Wbl + n * DIN + k8);
    }

    for (int c = 0; c < 24; c++) {
        // stage current chunk into smem (bf16 hi/lo)
#pragma unroll
        for (int i = 0; i < 4; i++) {
            int idx = i * 256 + tid;
            int r = idx >> 3, k4 = (idx & 7) * 4;
            float4 v = vx[i];
            __nv_bfloat16 hx = __float2bfloat16_rn(v.x);
            __nv_bfloat16 hy = __float2bfloat16_rn(v.y);
            __nv_bfloat16 hz = __float2bfloat16_rn(v.z);
            __nv_bfloat16 hw = __float2bfloat16_rn(v.w);
            *(__nv_bfloat162*)&Xh[r * XPITCH + k4 + 0] = __nv_bfloat162(hx, hy);
            *(__nv_bfloat162*)&Xh[r * XPITCH + k4 + 2] = __nv_bfloat162(hz, hw);
            *(__nv_bfloat162*)&Xl[r * XPITCH + k4 + 0] = __nv_bfloat162(
                __float2bfloat16_rn(v.x - __bfloat162float(hx)),
                __float2bfloat16_rn(v.y - __bfloat162float(hy)));
            *(__nv_bfloat162*)&Xl[r * XPITCH + k4 + 2] = __nv_bfloat162(
                __float2bfloat16_rn(v.z - __bfloat162float(hz)),
                __float2bfloat16_rn(v.w - __bfloat162float(hw)));
        }
#pragma unroll
        for (int i = 0; i < 2; i++) {
            int idx = i * 256 + tid;
            int n = idx >> 3, k8 = (idx & 7) * 4;
            *(ull*)&Wh[n * XPITCH + k8] = vwh[i];
            *(ull*)&Wl[n * XPITCH + k8] = vwl[i];
        }
        __syncthreads();

        // prefetch next chunk
        if (c < 23) {
            int k0 = (c + 1) * 32;
#pragma unroll
            for (int i = 0; i < 4; i++) {
                int idx = i * 256 + tid;
                int r = idx >> 3, k4 = (idx & 7) * 4;
                vx[i] = *(const float4*)(X + (size_t)(rowBase + r) * DIN + k0 + k4);
            }
#pragma unroll
            for (int i = 0; i < 2; i++) {
                int idx = i * 256 + tid;
                int n = idx >> 3, k8 = (idx & 7) * 4;
                vwh[i] = *(const ull*)(g_Wbh + n * DIN + k0 + k8);
                vwl[i] = *(const ull*)(g_Wbl + n * DIN + k0 + k8);
            }
        }

        // compute: 2 k16 steps
#pragma unroll
        for (int ks = 0; ks < 2; ks++) {
            const int kb = ks * 16 + 2 * t4;
            const int r0 = (w * 16 + g) * XPITCH;
            uint32 ah[4], al[4];
            ah[0] = *(const uint32*)&Xh[r0 + kb];
            ah[1] = *(const uint32*)&Xh[r0 + 8 * XPITCH + kb];
            ah[2] = *(const uint32*)&Xh[r0 + kb + 8];
            ah[3] = *(const uint32*)&Xh[r0 + 8 * XPITCH + kb + 8];
            al[0] = *(const uint32*)&Xl[r0 + kb];
            al[1] = *(const uint32*)&Xl[r0 + 8 * XPITCH + kb];
            al[2] = *(const uint32*)&Xl[r0 + kb + 8];
            al[3] = *(const uint32*)&Xl[r0 + 8 * XPITCH + kb + 8];
#pragma unroll
            for (int nt = 0; nt < 8; nt++) {
                int n = nt * 8 + g;
                uint32 bh[2], bl[2];
                bh[0] = *(const uint32*)&Wh[n * XPITCH + kb];
                bh[1] = *(const uint32*)&Wh[n * XPITCH + kb + 8];
                bl[0] = *(const uint32*)&Wl[n * XPITCH + kb];
                bl[1] = *(const uint32*)&Wl[n * XPITCH + kb + 8];
                mma_bf16(acc[nt], ah, bh);
                mma_bf16(acc[nt], ah, bl);
                mma_bf16(acc[nt], al, bh);
            }
        }
        __syncthreads();
    }

    // write out with bias
    const int r0 = rowBase + w * 16 + g;
#pragma unroll
    for (int nt = 0; nt < 8; nt++) {
        int cbase = nt * 8 + 2 * t4;
        float b0 = g_bc[cbase], b1 = g_bc[cbase + 1];
        *(float2*)(g_xproj + (size_t)r0 * 64 + cbase) = make_float2(acc[nt][0] + b0, acc[nt][1] + b1);
        *(float2*)(g_xproj + (size_t)(r0 + 8) * 64 + cbase) = make_float2(acc[nt][2] + b0, acc[nt][3] + b1);
    }
}

// ---------------- K2: bi-LSTM scan, 64-thread blocks x 128 blocks ----------------
__global__ __launch_bounds__(64) void k_bilstm(
    const float* __restrict__ Whh_f, const float* __restrict__ Whh_b)
{
    int gt = blockIdx.x * 64 + threadIdx.x;  // 0..8191
    int j   = gt & 7;
    int grp = gt >> 3;        // 0..1023
    int dir = grp >> 9;       // 0 fwd, 1 bwd
    int b   = grp & 511;
    const float* Whh = dir ? Whh_b : Whh_f;

    float w[4][8];
#pragma unroll
    for (int gi = 0; gi < 4; gi++)
#pragma unroll
        for (int k = 0; k < 8; k++) w[gi][k] = Whh[(gi * 8 + j) * 8 + k];

    float h = 0.f, c = 0.f;
    const int lanebase = (threadIdx.x & 31) & ~7;

    // 2-deep prefetch
    int t0 = dir ? (T_LEN - 1) : 0;
    int t1 = dir ? (T_LEN - 2) : 1;
    const float* xp0 = g_xproj + ((size_t)t0 * BATCH + b) * 64 + dir * 32;
    const float* xp1 = g_xproj + ((size_t)t1 * BATCH + b) * 64 + dir * 32;
    float n0 = xp0[j], n1 = xp0[8 + j], n2 = xp0[16 + j], n3 = xp0[24 + j];
    float m0 = xp1[j], m1 = xp1[8 + j], m2 = xp1[16 + j], m3 = xp1[24 + j];

    for (int s = 0; s < T_LEN; s++) {
        int t = dir ? (T_LEN - 1 - s) : s;
        float p0 = n0, p1 = n1, p2 = n2, p3 = n3;
        n0 = m0; n1 = m1; n2 = m2; n3 = m3;
        if (s < T_LEN - 2) {
            int tn = dir ? (T_LEN - 3 - s) : (s + 2);
            const float* xn = g_xproj + ((size_t)tn * BATCH + b) * 64 + dir * 32;
            m0 = xn[j]; m1 = xn[8 + j]; m2 = xn[16 + j]; m3 = xn[24 + j];
        }
#pragma unroll
        for (int k = 0; k < 8; k++) {
            float hk = __shfl_sync(0xffffffffu, h, lanebase + k);
            p0 += w[0][k] * hk;
            p1 += w[1][k] * hk;
            p2 += w[2][k] * hk;
            p3 += w[3][k] * hk;
        }
        float ig = sigf(p0), fg = sigf(p1), gg = tanhf_fast(p2), og = sigf(p3);
        c = fg * c + ig * gg;
        h = og * tanhf_fast(c);
        g_h[((size_t)t * BATCH + b) * 16 + dir * 8 + j] = h;
    }
}

// ---------------- K3a: zproj = h (65536x16) @ Wih_p^T + bias, smem-staged coalesced ----------------
__global__ __launch_bounds__(128) void k_hproj(
    const float* __restrict__ Wih_p, const float* __restrict__ bih_p, const float* __restrict__ bhh_p)
{
    __shared__ float Wp[1024];
    __shared__ float bp[64];
    __shared__ float obuf[128 * 65];
    int tid = threadIdx.x;
    for (int i = tid; i < 1024; i += 128) Wp[i] = Wih_p[i];
    if (tid < 64) bp[tid] = bih_p[tid] + bhh_p[tid];
    __syncthreads();

    int row = blockIdx.x * 128 + tid;
    float hreg[16];
    const float4* hp = (const float4*)(g_h + (size_t)row * 16);
#pragma unroll
    for (int q = 0; q < 4; q++) {
        float4 v = hp[q];
        hreg[4 * q + 0] = v.x; hreg[4 * q + 1] = v.y; hreg[4 * q + 2] = v.z; hreg[4 * q + 3] = v.w;
    }
    float* orow = obuf + tid * 65;
#pragma unroll
    for (int r = 0; r < 64; r += 4) {
        float a0 = bp[r], a1 = bp[r + 1], a2 = bp[r + 2], a3 = bp[r + 3];
#pragma unroll
        for (int k = 0; k < 16; k++) {
            float hk = hreg[k];
            a0 += Wp[(r + 0) * 16 + k] * hk;
            a1 += Wp[(r + 1) * 16 + k] * hk;
            a2 += Wp[(r + 2) * 16 + k] * hk;
            a3 += Wp[(r + 3) * 16 + k] * hk;
        }
        orow[r] = a0; orow[r + 1] = a1; orow[r + 2] = a2; orow[r + 3] = a3;
    }
    __syncthreads();
    float* gout = g_zproj + (size_t)blockIdx.x * 128 * 64;
    for (int i = tid; i < 128 * 64; i += 128)
        gout[i] = obuf[(i >> 6) * 65 + (i & 63)];
}

// ---------------- K3b: ptr-LSTM scan, 64-thread blocks x 128 blocks ----------------
__global__ __launch_bounds__(64) void k_ptrlstm(const float* __restrict__ Whh_p)
{
    int gt = blockIdx.x * 64 + threadIdx.x;  // 0..8191
    int j = gt & 15;
    int b = gt >> 4;  // 0..511

    float w[4][16];
#pragma unroll
    for (int gi = 0; gi < 4; gi++)
#pragma unroll
        for (int k = 0; k < 16; k++) w[gi][k] = Whh_p[(gi * 16 + j) * 16 + k];

    float h = 0.f, c = 0.f;
    const int lanebase = (threadIdx.x & 31) & ~15;

    // 2-deep prefetch
    const float* zp0 = g_zproj + (size_t)b * 64;
    const float* zp1 = g_zproj + ((size_t)BATCH + b) * 64;
    float n0 = zp0[j], n1 = zp0[16 + j], n2 = zp0[32 + j], n3 = zp0[48 + j];
    float m0 = zp1[j], m1 = zp1[16 + j], m2 = zp1[32 + j], m3 = zp1[48 + j];

    for (int t = 0; t < T_LEN; t++) {
        float p0 = n0, p1 = n1, p2 = n2, p3 = n3;
        n0 = m0; n1 = m1; n2 = m2; n3 = m3;
        if (t < T_LEN - 2) {
            const float* zn = g_zproj + ((size_t)(t + 2) * BATCH + b) * 64;
            m0 = zn[j]; m1 = zn[16 + j]; m2 = zn[32 + j]; m3 = zn[48 + j];
        }
#pragma unroll
        for (int k = 0; k < 16; k++) {
            float hk = __shfl_sync(0xffffffffu, h, lanebase + k);
            p0 += w[0][k] * hk;
            p1 += w[1][k] * hk;
            p2 += w[2][k] * hk;
            p3 += w[3][k] * hk;
        }
        float ig = sigf(p0), fg = sigf(p1), gg = tanhf_fast(p2), og = sigf(p3);
        c = fg * c + ig * gg;
        h = og * tanhf_fast(c);
        g_z[((size_t)t * BATCH + b) * 16 + j] = h;
    }
}

// ---------------- K4: attention + output head, one CTA per t ----------------
__global__ __launch_bounds__(512, 1) void k_attn(
    const float* __restrict__ W_h, const float* __restrict__ W_e,
    const float* __restrict__ W_v, float* __restrict__ out)
{
    extern __shared__ float dsm[];
    float* sh = dsm;          // 512*16 floats (h_t, later overwritten by h/s_c)
    float* sz = dsm + 8192;   // 512*16 floats (z_t)
    __shared__ float sWh[256], sWe[256], sWv[16];

    const int t = blockIdx.x, tid = threadIdx.x;
    const float LOG2E = 1.4426950408889634f;
    const float* hg = g_h + (size_t)t * 8192;
    const float* zg = g_z + (size_t)t * 8192;
    for (int i = tid; i < 2048; i += 512) {
        ((float4*)sh)[i] = ((const float4*)hg)[i];
        ((float4*)sz)[i] = ((const float4*)zg)[i];
    }
    if (tid < 256) { sWh[tid] = W_h[tid]; sWe[tid] = W_e[tid]; }
    if (tid < 16)  sWv[tid] = W_v[tid];
    __syncthreads();

    // pass 1: thread owns column c = tid, s_c = sum_b exp(h_b . z_c)
    ull zc2[8];
    {
        const float* zr = sz + tid * 16;
        ull l2 = pack2(LOG2E, LOG2E);
#pragma unroll
        for (int q = 0; q < 4; q++) {
            union { float4 f; ull u[2]; } wv; wv.f = ((const float4*)zr)[q];
            zc2[2 * q]     = fma2(wv.u[0], l2, 0ULL);
            zc2[2 * q + 1] = fma2(wv.u[1], l2, 0ULL);
        }
    }
    float s0 = 0.f, s1 = 0.f;
#pragma unroll 4
    for (int bb = 0; bb < 512; bb += 2) {
        s0 += ex2f(dot16x2(sh + bb * 16, zc2));
        s1 += ex2f(dot16x2(sh + bb * 16 + 16, zc2));
    }
    float inv = __fdividef(1.f, s0 + s1);

    // stash original h row in regs (scaled copy for dots), then scale smem h by 1/s
    ull hb2[8]; float hb[16];
    {
        const float* hr = sh + tid * 16;
        ull l2 = pack2(LOG2E, LOG2E);
#pragma unroll
        for (int q = 0; q < 4; q++) {
            union { float4 f; ull u[2]; } wv; wv.f = ((const float4*)hr)[q];
            hb2[2 * q]     = fma2(wv.u[0], l2, 0ULL);
            hb2[2 * q + 1] = fma2(wv.u[1], l2, 0ULL);
            hb[4 * q + 0] = wv.f.x; hb[4 * q + 1] = wv.f.y; hb[4 * q + 2] = wv.f.z; hb[4 * q + 3] = wv.f.w;
        }
    }
    __syncthreads();
    {
        float* hr = sh + tid * 16;
#pragma unroll
        for (int q = 0; q < 4; q++)
            ((float4*)hr)[q] = make_float4(hb[4 * q] * inv, hb[4 * q + 1] * inv,
                                           hb[4 * q + 2] * inv, hb[4 * q + 3] * inv);
    }
    __syncthreads();

    // pass 2: thread owns row b = tid: ctx[b] = sum_c exp(h_b . z_c) * (h_c / s_c)
    ull ctx2[8];
#pragma unroll
    for (int q = 0; q < 8; q++) ctx2[q] = 0ULL;
#pragma unroll 2
    for (int cc = 0; cc < 512; cc++) {
        float s = dot16x2(sz + cc * 16, hb2);
        float e = ex2f(s);
        ull e2 = pack2(e, e);
        const float* hd = sh + cc * 16;
#pragma unroll
        for (int q = 0; q < 4; q++) {
            union { float4 f; ull u[2]; } wv; wv.f = ((const float4*)hd)[q];
            ctx2[2 * q]     = fma2(e2, wv.u[0], ctx2[2 * q]);
            ctx2[2 * q + 1] = fma2(e2, wv.u[1], ctx2[2 * q + 1]);
        }
    }
    float ctx[16];
#pragma unroll
    for (int q = 0; q < 8; q++) {
        float2 v = unpack2(ctx2[q]);
        ctx[2 * q] = v.x; ctx[2 * q + 1] = v.y;
    }

    // head: u = tanh(h W_h^T + ctx W_e^T); p = sigmoid(u . W_v)
    float pv = 0.f;
#pragma unroll
    for (int r = 0; r < 16; r++) {
        float a = 0.f;
#pragma unroll
        for (int k = 0; k < 16; k++)
            a += sWh[r * 16 + k] * hb[k] + sWe[r * 16 + k] * ctx[k];
        pv += sWv[r] * tanhf_fast(a);
    }
    out[(size_t)t * BATCH + tid] = sigf(pv);
}

// ---------------- launch ----------------
extern "C" void kernel_launch(void* const* d_in, const int* in_sizes, int n_in,
                              void* d_out, int out_size)
{
    const float* X     = (const float*)d_in[0];
    const float* Wih_f = (const float*)d_in[1];
    const float* Whh_f = (const float*)d_in[2];
    const float* bih_f = (const float*)d_in[3];
    const float* bhh_f = (const float*)d_in[4];
    const float* Wih_b = (const float*)d_in[5];
    const float* Whh_b = (const float*)d_in[6];
    const float* bih_b = (const float*)d_in[7];
    const float* bhh_b = (const float*)d_in[8];
    const float* Wih_p = (const float*)d_in[9];
    const float* Whh_p = (const float*)d_in[10];
    const float* bih_p = (const float*)d_in[11];
    const float* bhh_p = (const float*)d_in[12];
    const float* W_h   = (const float*)d_in[13];
    const float* W_e   = (const float*)d_in[14];
    const float* W_v   = (const float*)d_in[15];
    float* out = (float*)d_out;

    cudaFuncSetAttribute((const void*)k_attn, cudaFuncAttributeMaxDynamicSharedMemorySize, 72 * 1024);

    k_prep<<<dim3(3, 64), 256>>>(Wih_f, Wih_b, bih_f, bhh_f, bih_b, bhh_b);
    k_gemm_xproj<<<(T_LEN * BATCH) / 128, 256>>>(X);
    k_bilstm<<<128, 64>>>(Whh_f, Whh_b);
    k_hproj<<<(T_LEN * BATCH) / 128, 128>>>(Wih_p, bih_p, bhh_p);
    k_ptrlstm<<<128, 64>>>(Whh_p);
    k_attn<<<T_LEN, 512, 65536>>>(W_h, W_e, W_v, out);
}

// round 4
// speedup vs baseline: 2.5354x; 1.3108x over previous
#include <cuda_runtime.h>
#include <cuda_bf16.h>

#define T_LEN 128
#define BATCH 512
#define DIN   768

typedef unsigned long long ull;
typedef unsigned int uint32;

// ---------------- scratch (static device arrays; no allocation) ----------------
static __device__ float g_xproj[T_LEN * BATCH * 64];   // bi-LSTM gate pre-activations (x part + bias)
static __device__ float g_h[T_LEN * BATCH * 16];       // concat(h_f, h_b)
static __device__ float g_zproj[T_LEN * BATCH * 64];   // ptr-LSTM x-projection + bias
static __device__ float g_z[T_LEN * BATCH * 16];       // ptr-LSTM hidden states
static __device__ __nv_bfloat16 g_Wbh[64 * DIN];       // bf16-hi of combined weight, [n][k]
static __device__ __nv_bfloat16 g_Wbl[64 * DIN];       // bf16-lo residual, [n][k]
static __device__ float g_bc[64];                      // combined bias

// ---------------- helpers ----------------
__device__ __forceinline__ float ex2f(float x) {
    float r; asm("ex2.approx.ftz.f32 %0, %1;" : "=f"(r) : "f"(x)); return r;
}
__device__ __forceinline__ float sigf(float x) {
    return __fdividef(1.f, 1.f + __expf(-x));
}
__device__ __forceinline__ float tanhf_fast(float x) {
    float e = __expf(2.f * x);
    return 1.f - __fdividef(2.f, e + 1.f);
}
// pack two f32 -> bf16x2 (lo -> low half, hi -> high half)
__device__ __forceinline__ uint32 packbf(float lo, float hi) {
    uint32 r; asm("cvt.rn.bf16x2.f32 %0, %1, %2;" : "=r"(r) : "f"(hi), "f"(lo)); return r;
}
__device__ __forceinline__ float bflo(uint32 p) { return __uint_as_float(p << 16); }
__device__ __forceinline__ float bfhi(uint32 p) { return __uint_as_float(p & 0xffff0000u); }

// bf16 mma m16n8k16, row.col, f32 accumulate
__device__ __forceinline__ void mma_bf16(float* d, const uint32* a, const uint32* b) {
    asm volatile(
        "mma.sync.aligned.m16n8k16.row.col.f32.bf16.bf16.f32 "
        "{%0,%1,%2,%3}, {%4,%5,%6,%7}, {%8,%9}, {%0,%1,%2,%3};"
        : "+f"(d[0]), "+f"(d[1]), "+f"(d[2]), "+f"(d[3])
        : "r"(a[0]), "r"(a[1]), "r"(a[2]), "r"(a[3]), "r"(b[0]), "r"(b[1]));
}

// ---------------- K0: build combined weight, bf16 hi/lo, transposed [n][k] ----------------
__global__ __launch_bounds__(256) void k_prep(
    const float* __restrict__ Wih_f, const float* __restrict__ Wih_b,
    const float* __restrict__ bih_f, const float* __restrict__ bhh_f,
    const float* __restrict__ bih_b, const float* __restrict__ bhh_b)
{
    int n = blockIdx.y;
    int k = blockIdx.x * 256 + threadIdx.x;
    float w = (n < 32) ? Wih_f[n * DIN + k] : Wih_b[(n - 32) * DIN + k];
    __nv_bfloat16 hi = __float2bfloat16_rn(w);
    float res = w - __bfloat162float(hi);
    g_Wbh[n * DIN + k] = hi;
    g_Wbl[n * DIN + k] = __float2bfloat16_rn(res);
    if (blockIdx.x == 0 && blockIdx.y == 0 && threadIdx.x < 64) {
        int i = threadIdx.x;
        g_bc[i] = (i < 32) ? (bih_f[i] + bhh_f[i]) : (bih_b[i - 32] + bhh_b[i - 32]);
    }
}

// ---------------- K1: xproj = X (65536x768) @ Wc (768x64) + bc  (bf16 tensor cores) ----------------
#define XPITCH 40
__global__ __launch_bounds__(256, 2) void k_gemm_xproj(const float* __restrict__ X)
{
    __shared__ __nv_bfloat16 Xh[128 * XPITCH];
    __shared__ __nv_bfloat16 Xl[128 * XPITCH];
    __shared__ __nv_bfloat16 Wh[64 * XPITCH];
    __shared__ __nv_bfloat16 Wl[64 * XPITCH];

    const int tid = threadIdx.x;
    const int rowBase = blockIdx.x * 128;
    const int w = tid >> 5;        // warp 0..7 -> rows w*16..w*16+15
    const int lane = tid & 31;
    const int g = lane >> 2;       // groupID 0..7
    const int t4 = lane & 3;       // threadID in group

    float acc[8][4];
#pragma unroll
    for (int nt = 0; nt < 8; nt++)
#pragma unroll
        for (int q = 0; q < 4; q++) acc[nt][q] = 0.f;

    float4 vx[4];
    ull vwh[2], vwl[2];

    // prefetch chunk 0
#pragma unroll
    for (int i = 0; i < 4; i++) {
        int idx = i * 256 + tid;
        int r = idx >> 3, k4 = (idx & 7) * 4;
        vx[i] = *(const float4*)(X + (size_t)(rowBase + r) * DIN + k4);
    }
#pragma unroll
    for (int i = 0; i < 2; i++) {
        int idx = i * 256 + tid;
        int n = idx >> 3, k8 = (idx & 7) * 4;
        vwh[i] = *(const ull*)(g_Wbh + n * DIN + k8);
        vwl[i] = *(const ull*)(g_Wbl + n * DIN + k8);
    }

    for (int c = 0; c < 24; c++) {
        // stage current chunk into smem (bf16 hi/lo)
#pragma unroll
        for (int i = 0; i < 4; i++) {
            int idx = i * 256 + tid;
            int r = idx >> 3, k4 = (idx & 7) * 4;
            float4 v = vx[i];
            __nv_bfloat16 hx = __float2bfloat16_rn(v.x);
            __nv_bfloat16 hy = __float2bfloat16_rn(v.y);
            __nv_bfloat16 hz = __float2bfloat16_rn(v.z);
            __nv_bfloat16 hw = __float2bfloat16_rn(v.w);
            *(__nv_bfloat162*)&Xh[r * XPITCH + k4 + 0] = __nv_bfloat162(hx, hy);
            *(__nv_bfloat162*)&Xh[r * XPITCH + k4 + 2] = __nv_bfloat162(hz, hw);
            *(__nv_bfloat162*)&Xl[r * XPITCH + k4 + 0] = __nv_bfloat162(
                __float2bfloat16_rn(v.x - __bfloat162float(hx)),
                __float2bfloat16_rn(v.y - __bfloat162float(hy)));
            *(__nv_bfloat162*)&Xl[r * XPITCH + k4 + 2] = __nv_bfloat162(
                __float2bfloat16_rn(v.z - __bfloat162float(hz)),
                __float2bfloat16_rn(v.w - __bfloat162float(hw)));
        }
#pragma unroll
        for (int i = 0; i < 2; i++) {
            int idx = i * 256 + tid;
            int n = idx >> 3, k8 = (idx & 7) * 4;
            *(ull*)&Wh[n * XPITCH + k8] = vwh[i];
            *(ull*)&Wl[n * XPITCH + k8] = vwl[i];
        }
        __syncthreads();

        // prefetch next chunk
        if (c < 23) {
            int k0 = (c + 1) * 32;
#pragma unroll
            for (int i = 0; i < 4; i++) {
                int idx = i * 256 + tid;
                int r = idx >> 3, k4 = (idx & 7) * 4;
                vx[i] = *(const float4*)(X + (size_t)(rowBase + r) * DIN + k0 + k4);
            }
#pragma unroll
            for (int i = 0; i < 2; i++) {
                int idx = i * 256 + tid;
                int n = idx >> 3, k8 = (idx & 7) * 4;
                vwh[i] = *(const ull*)(g_Wbh + n * DIN + k0 + k8);
                vwl[i] = *(const ull*)(g_Wbl + n * DIN + k0 + k8);
            }
        }

        // compute: 2 k16 steps
#pragma unroll
        for (int ks = 0; ks < 2; ks++) {
            const int kb = ks * 16 + 2 * t4;
            const int r0 = (w * 16 + g) * XPITCH;
            uint32 ah[4], al[4];
            ah[0] = *(const uint32*)&Xh[r0 + kb];
            ah[1] = *(const uint32*)&Xh[r0 + 8 * XPITCH + kb];
            ah[2] = *(const uint32*)&Xh[r0 + kb + 8];
            ah[3] = *(const uint32*)&Xh[r0 + 8 * XPITCH + kb + 8];
            al[0] = *(const uint32*)&Xl[r0 + kb];
            al[1] = *(const uint32*)&Xl[r0 + 8 * XPITCH + kb];
            al[2] = *(const uint32*)&Xl[r0 + kb + 8];
            al[3] = *(const uint32*)&Xl[r0 + 8 * XPITCH + kb + 8];
#pragma unroll
            for (int nt = 0; nt < 8; nt++) {
                int n = nt * 8 + g;
                uint32 bh[2], bl[2];
                bh[0] = *(const uint32*)&Wh[n * XPITCH + kb];
                bh[1] = *(const uint32*)&Wh[n * XPITCH + kb + 8];
                bl[0] = *(const uint32*)&Wl[n * XPITCH + kb];
                bl[1] = *(const uint32*)&Wl[n * XPITCH + kb + 8];
                mma_bf16(acc[nt], ah, bh);
                mma_bf16(acc[nt], ah, bl);
                mma_bf16(acc[nt], al, bh);
            }
        }
        __syncthreads();
    }

    // write out with bias
    const int r0 = rowBase + w * 16 + g;
#pragma unroll
    for (int nt = 0; nt < 8; nt++) {
        int cbase = nt * 8 + 2 * t4;
        float b0 = g_bc[cbase], b1 = g_bc[cbase + 1];
        *(float2*)(g_xproj + (size_t)r0 * 64 + cbase) = make_float2(acc[nt][0] + b0, acc[nt][1] + b1);
        *(float2*)(g_xproj + (size_t)(r0 + 8) * 64 + cbase) = make_float2(acc[nt][2] + b0, acc[nt][3] + b1);
    }
}

// ---------------- K2: bi-LSTM scan, 64-thread blocks x 128 blocks ----------------
__global__ __launch_bounds__(64) void k_bilstm(
    const float* __restrict__ Whh_f, const float* __restrict__ Whh_b)
{
    int gt = blockIdx.x * 64 + threadIdx.x;  // 0..8191
    int j   = gt & 7;
    int grp = gt >> 3;        // 0..1023
    int dir = grp >> 9;       // 0 fwd, 1 bwd
    int b   = grp & 511;
    const float* Whh = dir ? Whh_b : Whh_f;

    float w[4][8];
#pragma unroll
    for (int gi = 0; gi < 4; gi++)
#pragma unroll
        for (int k = 0; k < 8; k++) w[gi][k] = Whh[(gi * 8 + j) * 8 + k];

    float h = 0.f, c = 0.f;
    const int lanebase = (threadIdx.x & 31) & ~7;

    // 2-deep prefetch
    int t0 = dir ? (T_LEN - 1) : 0;
    int t1 = dir ? (T_LEN - 2) : 1;
    const float* xp0 = g_xproj + ((size_t)t0 * BATCH + b) * 64 + dir * 32;
    const float* xp1 = g_xproj + ((size_t)t1 * BATCH + b) * 64 + dir * 32;
    float n0 = xp0[j], n1 = xp0[8 + j], n2 = xp0[16 + j], n3 = xp0[24 + j];
    float m0 = xp1[j], m1 = xp1[8 + j], m2 = xp1[16 + j], m3 = xp1[24 + j];

    for (int s = 0; s < T_LEN; s++) {
        int t = dir ? (T_LEN - 1 - s) : s;
        float p0 = n0, p1 = n1, p2 = n2, p3 = n3;
        n0 = m0; n1 = m1; n2 = m2; n3 = m3;
        if (s < T_LEN - 2) {
            int tn = dir ? (T_LEN - 3 - s) : (s + 2);
            const float* xn = g_xproj + ((size_t)tn * BATCH + b) * 64 + dir * 32;
            m0 = xn[j]; m1 = xn[8 + j]; m2 = xn[16 + j]; m3 = xn[24 + j];
        }
#pragma unroll
        for (int k = 0; k < 8; k++) {
            float hk = __shfl_sync(0xffffffffu, h, lanebase + k);
            p0 += w[0][k] * hk;
            p1 += w[1][k] * hk;
            p2 += w[2][k] * hk;
            p3 += w[3][k] * hk;
        }
        float ig = sigf(p0), fg = sigf(p1), gg = tanhf_fast(p2), og = sigf(p3);
        c = fg * c + ig * gg;
        h = og * tanhf_fast(c);
        g_h[((size_t)t * BATCH + b) * 16 + dir * 8 + j] = h;
    }
}

// ---------------- K3a: zproj = h (65536x16) @ Wih_p^T + bias, smem-staged coalesced ----------------
__global__ __launch_bounds__(128) void k_hproj(
    const float* __restrict__ Wih_p, const float* __restrict__ bih_p, const float* __restrict__ bhh_p)
{
    __shared__ float Wp[1024];
    __shared__ float bp[64];
    __shared__ float obuf[128 * 65];
    int tid = threadIdx.x;
    for (int i = tid; i < 1024; i += 128) Wp[i] = Wih_p[i];
    if (tid < 64) bp[tid] = bih_p[tid] + bhh_p[tid];
    __syncthreads();

    int row = blockIdx.x * 128 + tid;
    float hreg[16];
    const float4* hp = (const float4*)(g_h + (size_t)row * 16);
#pragma unroll
    for (int q = 0; q < 4; q++) {
        float4 v = hp[q];
        hreg[4 * q + 0] = v.x; hreg[4 * q + 1] = v.y; hreg[4 * q + 2] = v.z; hreg[4 * q + 3] = v.w;
    }
    float* orow = obuf + tid * 65;
#pragma unroll
    for (int r = 0; r < 64; r += 4) {
        float a0 = bp[r], a1 = bp[r + 1], a2 = bp[r + 2], a3 = bp[r + 3];
#pragma unroll
        for (int k = 0; k < 16; k++) {
            float hk = hreg[k];
            a0 += Wp[(r + 0) * 16 + k] * hk;
            a1 += Wp[(r + 1) * 16 + k] * hk;
            a2 += Wp[(r + 2) * 16 + k] * hk;
            a3 += Wp[(r + 3) * 16 + k] * hk;
        }
        orow[r] = a0; orow[r + 1] = a1; orow[r + 2] = a2; orow[r + 3] = a3;
    }
    __syncthreads();
    float* gout = g_zproj + (size_t)blockIdx.x * 128 * 64;
    for (int i = tid; i < 128 * 64; i += 128)
        gout[i] = obuf[(i >> 6) * 65 + (i & 63)];
}

// ---------------- K3b: ptr-LSTM scan, 64-thread blocks x 128 blocks ----------------
__global__ __launch_bounds__(64) void k_ptrlstm(const float* __restrict__ Whh_p)
{
    int gt = blockIdx.x * 64 + threadIdx.x;  // 0..8191
    int j = gt & 15;
    int b = gt >> 4;  // 0..511

    float w[4][16];
#pragma unroll
    for (int gi = 0; gi < 4; gi++)
#pragma unroll
        for (int k = 0; k < 16; k++) w[gi][k] = Whh_p[(gi * 16 + j) * 16 + k];

    float h = 0.f, c = 0.f;
    const int lanebase = (threadIdx.x & 31) & ~15;

    // 2-deep prefetch
    const float* zp0 = g_zproj + (size_t)b * 64;
    const float* zp1 = g_zproj + ((size_t)BATCH + b) * 64;
    float n0 = zp0[j], n1 = zp0[16 + j], n2 = zp0[32 + j], n3 = zp0[48 + j];
    float m0 = zp1[j], m1 = zp1[16 + j], m2 = zp1[32 + j], m3 = zp1[48 + j];

    for (int t = 0; t < T_LEN; t++) {
        float p0 = n0, p1 = n1, p2 = n2, p3 = n3;
        n0 = m0; n1 = m1; n2 = m2; n3 = m3;
        if (t < T_LEN - 2) {
            const float* zn = g_zproj + ((size_t)(t + 2) * BATCH + b) * 64;
            m0 = zn[j]; m1 = zn[16 + j]; m2 = zn[32 + j]; m3 = zn[48 + j];
        }
#pragma unroll
        for (int k = 0; k < 16; k++) {
            float hk = __shfl_sync(0xffffffffu, h, lanebase + k);
            p0 += w[0][k] * hk;
            p1 += w[1][k] * hk;
            p2 += w[2][k] * hk;
            p3 += w[3][k] * hk;
        }
        float ig = sigf(p0), fg = sigf(p1), gg = tanhf_fast(p2), og = sigf(p3);
        c = fg * c + ig * gg;
        h = og * tanhf_fast(c);
        g_z[((size_t)t * BATCH + b) * 16 + j] = h;
    }
}

// ---------------- K4: tensor-core attention + output head, one CTA per t ----------------
// S[b,c] = h_b . z_c via bf16 hi/lo 3-term mma (z pre-scaled by log2e).
// E = 2^S; colsum over b per c; ctx[b] = sum_c E[b,c]*inv_c*h[c] via second mma
// whose A-fragments are EXACTLY the exp'd D-fragments of the first (register reuse,
// no score matrix in memory). inv_c folded into the B operand (hT * inv, fp32->hi/lo).
#define HP 20            // bf16 pitch for h/z tiles (conflict-free fragment loads)
#define HTP 516          // fp32 pitch for hT[16][512]
#define OFF_HHI   0
#define OFF_HLO   20480
#define OFF_ZHI   40960
#define OFF_ZLO   61440
#define OFF_HT    81920
#define OFF_CP    114944
#define OFF_INV   117248
#define OFF_CTX   117376
#define OFF_WH    152192
#define OFF_WE    153216
#define OFF_WV    154240
#define ATT_SMEM  154304

__global__ __launch_bounds__(512, 1) void k_attn(
    const float* __restrict__ W_h, const float* __restrict__ W_e,
    const float* __restrict__ W_v, float* __restrict__ out)
{
    extern __shared__ char smc[];
    __nv_bfloat16* hhi = (__nv_bfloat16*)(smc + OFF_HHI);
    __nv_bfloat16* hlo = (__nv_bfloat16*)(smc + OFF_HLO);
    __nv_bfloat16* zhi = (__nv_bfloat16*)(smc + OFF_ZHI);
    __nv_bfloat16* zlo = (__nv_bfloat16*)(smc + OFF_ZLO);
    float* hT   = (float*)(smc + OFF_HT);
    float* cp   = (float*)(smc + OFF_CP);
    float* invs = (float*)(smc + OFF_INV);
    float* ctx  = (float*)(smc + OFF_CTX);
    float* sWh  = (float*)(smc + OFF_WH);
    float* sWe  = (float*)(smc + OFF_WE);
    float* sWv  = (float*)(smc + OFF_WV);

    const int t = blockIdx.x, tid = threadIdx.x;
    const int w = tid >> 5, lane = tid & 31;
    const int qr = lane >> 2, qc = lane & 3;
    const float LOG2E = 1.4426950408889634f;

    // ---- stage h, z into bf16 hi/lo (+ hT fp32 transpose); z scaled by log2e ----
    const float4* hg = (const float4*)(g_h + (size_t)t * 8192);
    const float4* zg = (const float4*)(g_z + (size_t)t * 8192);
#pragma unroll
    for (int it = 0; it < 4; it++) {
        int i = it * 512 + tid;
        int r = i >> 2, d4 = (i & 3) * 4;
        float4 v = hg[i];
        uint32 h01 = packbf(v.x, v.y), h23 = packbf(v.z, v.w);
        *(uint32*)&hhi[r * HP + d4]     = h01;
        *(uint32*)&hhi[r * HP + d4 + 2] = h23;
        *(uint32*)&hlo[r * HP + d4]     = packbf(v.x - bflo(h01), v.y - bfhi(h01));
        *(uint32*)&hlo[r * HP + d4 + 2] = packbf(v.z - bflo(h23), v.w - bfhi(h23));
        hT[(d4 + 0) * HTP + r] = v.x;
        hT[(d4 + 1) * HTP + r] = v.y;
        hT[(d4 + 2) * HTP + r] = v.z;
        hT[(d4 + 3) * HTP + r] = v.w;
        float4 u = zg[i];
        u.x *= LOG2E; u.y *= LOG2E; u.z *= LOG2E; u.w *= LOG2E;
        uint32 z01 = packbf(u.x, u.y), z23 = packbf(u.z, u.w);
        *(uint32*)&zhi[r * HP + d4]     = z01;
        *(uint32*)&zhi[r * HP + d4 + 2] = z23;
        *(uint32*)&zlo[r * HP + d4]     = packbf(u.x - bflo(z01), u.y - bfhi(z01));
        *(uint32*)&zlo[r * HP + d4 + 2] = packbf(u.z - bflo(z23), u.w - bfhi(z23));
    }
    if (tid < 256) { sWh[tid] = W_h[tid]; sWe[tid] = W_e[tid]; }
    if (tid < 16)  sWv[tid] = W_v[tid];
    __syncthreads();

    // ---- persistent A fragments: this warp's 32 h-rows (hi/lo) ----
    uint32 Ahh[2][4], Ahl[2][4];
#pragma unroll
    for (int mt = 0; mt < 2; mt++) {
        int row = 32 * w + 16 * mt + qr;
        int base = row * HP + 2 * qc;
        Ahh[mt][0] = *(const uint32*)&hhi[base];
        Ahh[mt][1] = *(const uint32*)&hhi[base + 8 * HP];
        Ahh[mt][2] = *(const uint32*)&hhi[base + 8];
        Ahh[mt][3] = *(const uint32*)&hhi[base + 8 * HP + 8];
        Ahl[mt][0] = *(const uint32*)&hlo[base];
        Ahl[mt][1] = *(const uint32*)&hlo[base + 8 * HP];
        Ahl[mt][2] = *(const uint32*)&hlo[base + 8];
        Ahl[mt][3] = *(const uint32*)&hlo[base + 8 * HP + 8];
    }

    float ctxacc[2][2][4];
#pragma unroll
    for (int mt = 0; mt < 2; mt++)
#pragma unroll
        for (int nt = 0; nt < 2; nt++)
#pragma unroll
            for (int q = 0; q < 4; q++) ctxacc[mt][nt][q] = 0.f;

    for (int tile = 0; tile < 16; tile++) {
        const int c0 = tile * 32;
        uint32 Aeh[2][2][4], Ael[2][2][4];   // [mt][ks][frag] exp'd scores as bf16 hi/lo

        // --- S tile (512x32) + exp + colsum partials ---
#pragma unroll
        for (int nt = 0; nt < 4; nt++) {
            int crow = c0 + 8 * nt + qr;
            int zb = crow * HP + 2 * qc;
            uint32 bzh[2], bzl[2];
            bzh[0] = *(const uint32*)&zhi[zb];
            bzh[1] = *(const uint32*)&zhi[zb + 8];
            bzl[0] = *(const uint32*)&zlo[zb];
            bzl[1] = *(const uint32*)&zlo[zb + 8];
            float P0 = 0.f, P1 = 0.f;
            const int ks = nt >> 1, hf = nt & 1;
#pragma unroll
            for (int mt = 0; mt < 2; mt++) {
                float S[4] = {0.f, 0.f, 0.f, 0.f};
                mma_bf16(S, Ahh[mt], bzh);
                mma_bf16(S, Ahh[mt], bzl);
                mma_bf16(S, Ahl[mt], bzh);
                float e0 = ex2f(S[0]), e1 = ex2f(S[1]), e2 = ex2f(S[2]), e3 = ex2f(S[3]);
                P0 += e0 + e2; P1 += e1 + e3;
                uint32 p01 = packbf(e0, e1), p23 = packbf(e2, e3);
                Aeh[mt][ks][2 * hf]     = p01;
                Aeh[mt][ks][2 * hf + 1] = p23;
                Ael[mt][ks][2 * hf]     = packbf(e0 - bflo(p01), e1 - bfhi(p01));
                Ael[mt][ks][2 * hf + 1] = packbf(e2 - bflo(p23), e3 - bfhi(p23));
            }
            P0 += __shfl_xor_sync(0xffffffffu, P0, 4);
            P0 += __shfl_xor_sync(0xffffffffu, P0, 8);
            P0 += __shfl_xor_sync(0xffffffffu, P0, 16);
            P1 += __shfl_xor_sync(0xffffffffu, P1, 4);
            P1 += __shfl_xor_sync(0xffffffffu, P1, 8);
            P1 += __shfl_xor_sync(0xffffffffu, P1, 16);
            if (qr == 0) {
                cp[w * 36 + 8 * nt + 2 * qc]     = P0;
                cp[w * 36 + 8 * nt + 2 * qc + 1] = P1;
            }
        }
        __syncthreads();
        if (tid < 32) {
            float s = 0.f;
#pragma unroll
            for (int ww = 0; ww < 16; ww++) s += cp[ww * 36 + tid];
            invs[tid] = __fdividef(1.f, s);
        }
        __syncthreads();

        // --- ctx += E * (hT * inv)^T  (3-term) ---
#pragma unroll
        for (int ks = 0; ks < 2; ks++) {
#pragma unroll
            for (int nt2 = 0; nt2 < 2; nt2++) {
                int d = 8 * nt2 + qr;
                int cc = 16 * ks + 2 * qc;
                float i0 = invs[cc], i1 = invs[cc + 1], i8 = invs[cc + 8], i9 = invs[cc + 9];
                const float* hr = hT + d * HTP + c0 + cc;
                float v0 = hr[0] * i0, v1 = hr[1] * i1, v8 = hr[8] * i8, v9 = hr[9] * i9;
                uint32 bh[2], bl[2];
                bh[0] = packbf(v0, v1);
                bh[1] = packbf(v8, v9);
                bl[0] = packbf(v0 - bflo(bh[0]), v1 - bfhi(bh[0]));
                bl[1] = packbf(v8 - bflo(bh[1]), v9 - bfhi(bh[1]));
#pragma unroll
                for (int mt = 0; mt < 2; mt++) {
                    mma_bf16(ctxacc[mt][nt2], Aeh[mt][ks], bh);
                    mma_bf16(ctxacc[mt][nt2], Ael[mt][ks], bh);
                    mma_bf16(ctxacc[mt][nt2], Aeh[mt][ks], bl);
                }
            }
        }
        // next tile's cp writes are safe: all warps passed the inv sync above
    }

    // ---- write ctx to smem ----
#pragma unroll
    for (int mt = 0; mt < 2; mt++)
#pragma unroll
        for (int nt2 = 0; nt2 < 2; nt2++) {
            int row = 32 * w + 16 * mt + qr;
            int col = 8 * nt2 + 2 * qc;
            ctx[row * 17 + col]           = ctxacc[mt][nt2][0];
            ctx[row * 17 + col + 1]       = ctxacc[mt][nt2][1];
            ctx[(row + 8) * 17 + col]     = ctxacc[mt][nt2][2];
            ctx[(row + 8) * 17 + col + 1] = ctxacc[mt][nt2][3];
        }
    __syncthreads();

    // ---- head: u = tanh(h W_h^T + ctx W_e^T); p = sigmoid(u . W_v) ----
    {
        int b = tid;
        float hb[16], cx[16];
        const float4* hp4 = (const float4*)(g_h + (size_t)t * 8192 + b * 16);
#pragma unroll
        for (int q = 0; q < 4; q++) {
            float4 v = hp4[q];
            hb[4 * q + 0] = v.x; hb[4 * q + 1] = v.y; hb[4 * q + 2] = v.z; hb[4 * q + 3] = v.w;
        }
#pragma unroll
        for (int k = 0; k < 16; k++) cx[k] = ctx[b * 17 + k];
        float pv = 0.f;
#pragma unroll
        for (int r = 0; r < 16; r++) {
            float a = 0.f;
#pragma unroll
            for (int k = 0; k < 16; k++)
                a += sWh[r * 16 + k] * hb[k] + sWe[r * 16 + k] * cx[k];
            pv += sWv[r] * tanhf_fast(a);
        }
        out[(size_t)t * BATCH + b] = sigf(pv);
    }
}

// ---------------- launch ----------------
extern "C" void kernel_launch(void* const* d_in, const int* in_sizes, int n_in,
                              void* d_out, int out_size)
{
    const float* X     = (const float*)d_in[0];
    const float* Wih_f = (const float*)d_in[1];
    const float* Whh_f = (const float*)d_in[2];
    const float* bih_f = (const float*)d_in[3];
    const float* bhh_f = (const float*)d_in[4];
    const float* Wih_b = (const float*)d_in[5];
    const float* Whh_b = (const float*)d_in[6];
    const float* bih_b = (const float*)d_in[7];
    const float* bhh_b = (const float*)d_in[8];
    const float* Wih_p = (const float*)d_in[9];
    const float* Whh_p = (const float*)d_in[10];
    const float* bih_p = (const float*)d_in[11];
    const float* bhh_p = (const float*)d_in[12];
    const float* W_h   = (const float*)d_in[13];
    const float* W_e   = (const float*)d_in[14];
    const float* W_v   = (const float*)d_in[15];
    float* out = (float*)d_out;

    cudaFuncSetAttribute((const void*)k_attn, cudaFuncAttributeMaxDynamicSharedMemorySize, 160 * 1024);

    k_prep<<<dim3(3, 64), 256>>>(Wih_f, Wih_b, bih_f, bhh_f, bih_b, bhh_b);
    k_gemm_xproj<<<(T_LEN * BATCH) / 128, 256>>>(X);
    k_bilstm<<<128, 64>>>(Whh_f, Whh_b);
    k_hproj<<<(T_LEN * BATCH) / 128, 128>>>(Wih_p, bih_p, bhh_p);
    k_ptrlstm<<<128, 64>>>(Whh_p);
    k_attn<<<T_LEN, 512, ATT_SMEM>>>(W_h, W_e, W_v, out);
}